// round 3
// baseline (speedup 1.0000x reference)
#include <cuda_runtime.h>

constexpr int C_   = 192;
constexpr int H_   = 192;
constexpr int W_   = 192;
constexpr int SS_  = 4;
constexpr int NH_  = 6;
constexpr int NWIN = 8 * 24 * 24;   // 4608
constexpr int HW_  = H_ * W_;

__device__ float g_qkv[(size_t)NWIN * 3 * NH_ * 64 * 32];  // [b_][s][h][n][d]
__device__ float g_att[(size_t)NWIN * 64 * 192];           // [b_*64+n][c]

typedef unsigned long long ull;

__device__ __forceinline__ ull dup2(float x) {
    ull r; asm("mov.b64 %0,{%1,%1};" : "=l"(r) : "f"(x)); return r;
}
__device__ __forceinline__ void upk2(ull v, float& x, float& y) {
    asm("mov.b64 {%0,%1},%2;" : "=f"(x), "=f"(y) : "l"(v));
}
__device__ __forceinline__ ull ffma2(ull a, ull b, ull c) {
    ull d; asm("fma.rn.f32x2 %0,%1,%2,%3;" : "=l"(d) : "l"(a), "l"(b), "l"(c));
    return d;
}

// =====================================================================
// Kernel 1: gather rolled window + QKV projection
// grid=4608, block=256, 2 CTAs/SM.
// smem: xs[192][64] (48K) + wsm[192][66] (49.5K) = 99840 B
// 9 output chunks of 64; thread tile 4 tokens x 2 output-pairs.
// =====================================================================
__global__ __launch_bounds__(256, 2)
void k_qkv(const float* __restrict__ x, const float* __restrict__ w,
           const float* __restrict__ bias) {
    extern __shared__ float sm[];
    float* xs  = sm;               // [192][64]
    float* wsm = sm + 192 * 64;    // [192][66]
    __shared__ int soff[64];

    const int b_  = blockIdx.x;
    const int b   = b_ / 576;
    const int wh  = (b_ % 576) / 24;
    const int ww  = b_ % 24;
    const int tid = threadIdx.x;

    if (tid < 64) {
        int ph = tid >> 3, pw = tid & 7;
        int sh = wh * 8 + ph + SS_; if (sh >= H_) sh -= H_;
        int sw = ww * 8 + pw + SS_; if (sw >= W_) sw -= W_;
        soff[tid] = sh * W_ + sw;
    }
    __syncthreads();

    const float* xb = x + (size_t)b * C_ * HW_;
    #pragma unroll
    for (int i = 0; i < 48; i++) {
        int idx = tid + i * 256;
        int c = idx >> 6, t = idx & 63;
        xs[c * 64 + t] = xb[c * HW_ + soff[t]];
    }

    const int ty = tid >> 4, tx = tid & 15, t0 = ty * 4;
    float* gout = g_qkv + (size_t)b_ * 3 * 6 * 64 * 32;

    for (int ch = 0; ch < 9; ch++) {
        __syncthreads();   // previous chunk's wsm reads complete
        // stage weight rows [64*ch, 64*ch+64), transposed to k-major
        const float* wb = w + ch * 64 * 192;
        #pragma unroll
        for (int i = 0; i < 48; i++) {
            int idx = tid + i * 256;
            int o = idx / 192, k = idx - o * 192;
            wsm[k * 66 + o] = wb[o * 192 + k];
        }
        __syncthreads();

        ull acc[4][2];
        {
            ull b0 = *(const ull*)&bias[ch * 64 + 2 * tx];
            ull b1 = *(const ull*)&bias[ch * 64 + 2 * tx + 32];
            #pragma unroll
            for (int t = 0; t < 4; t++) { acc[t][0] = b0; acc[t][1] = b1; }
        }

        #pragma unroll 4
        for (int k = 0; k < 192; k++) {
            float4 af = *(const float4*)&xs[k * 64 + t0];
            ull a0 = dup2(af.x), a1 = dup2(af.y), a2 = dup2(af.z), a3 = dup2(af.w);
            const ull* wr = (const ull*)&wsm[k * 66 + 2 * tx];
            ull bv0 = wr[0], bv1 = wr[16];
            acc[0][0] = ffma2(a0, bv0, acc[0][0]);
            acc[1][0] = ffma2(a1, bv0, acc[1][0]);
            acc[2][0] = ffma2(a2, bv0, acc[2][0]);
            acc[3][0] = ffma2(a3, bv0, acc[3][0]);
            acc[0][1] = ffma2(a0, bv1, acc[0][1]);
            acc[1][1] = ffma2(a1, bv1, acc[1][1]);
            acc[2][1] = ffma2(a2, bv1, acc[2][1]);
            acc[3][1] = ffma2(a3, bv1, acc[3][1]);
        }

        // chunk ch covers outputs [64ch, 64ch+64): s = ch/3,
        // h = 2*(ch%3)+j, d = 2*tx  (32|j picks the head half)
        const int s  = ch / 3;
        const int r3 = ch - 3 * s;
        const float sc = (s == 0) ? 0.17677669529663687f : 1.0f;
        #pragma unroll
        for (int j = 0; j < 2; j++) {
            const int hh = 2 * r3 + j;
            float* go = gout + ((size_t)(s * 6 + hh) * 64) * 32 + 2 * tx;
            #pragma unroll
            for (int t = 0; t < 4; t++) {
                float xx, yy;
                upk2(acc[t][j], xx, yy);
                *(float2*)&go[(t0 + t) * 32] = make_float2(xx * sc, yy * sc);
            }
        }
    }
}

// =====================================================================
// Kernel 2: fused single-pass windowed attention
// grid=4608, block=192 (warp h, lane r handles query rows r and r+32)
// smem: ks[6][64][32] + vs[6][64][32] + tb[6][228] + ids[64] = 104032 B
// No max-subtraction: logits in [-100, ~1]; expf exact, mask -> 0.
// =====================================================================
__global__ __launch_bounds__(192, 2)
void k_attn(const float* __restrict__ tbl) {
    extern __shared__ float sm[];
    float* ks = sm;               // 12288 floats
    float* vs = sm + 12288;       // 12288 floats
    float* tb = sm + 24576;       // 6*228
    int*  ids = (int*)(sm + 24576 + 1368);

    const int b_  = blockIdx.x;
    const int wh  = (b_ % 576) / 24;
    const int ww  = b_ % 24;
    const int tid = threadIdx.x;
    const int h   = tid >> 5;
    const int r   = tid & 31;

    const float* base = g_qkv + (size_t)b_ * 3 * 12288;

    {
        const float4* srck = (const float4*)(base + 12288);
        const float4* srcv = (const float4*)(base + 24576);
        float4* dk = (float4*)ks;
        float4* dv = (float4*)vs;
        #pragma unroll
        for (int i = 0; i < 16; i++) {
            int idx = tid + i * 192;
            dk[idx] = srck[idx];
            dv[idx] = srcv[idx];
        }
    }
    for (int i = tid; i < 1350; i += 192) {
        int hh = i % 6, ii = i / 6;
        tb[hh * 228 + ii] = tbl[i];
    }
    if (tid < 64) {
        int ph = tid >> 3, pw = tid & 7;
        int gh = wh * 8 + ph, gw = ww * 8 + pw;
        int rh = gh < (H_ - 8) ? 0 : (gh < (H_ - 4) ? 1 : 2);
        int rw = gw < (W_ - 8) ? 0 : (gw < (W_ - 4) ? 1 : 2);
        ids[tid] = rh * 3 + rw;
    }

    const int rA = r, rB = r + 32;
    ull qA[16], qB[16];
    {
        const ull* qa = (const ull*)(base + (size_t)(h * 64 + rA) * 32);
        const ull* qb = (const ull*)(base + (size_t)(h * 64 + rB) * 32);
        #pragma unroll
        for (int i = 0; i < 16; i++) { qA[i] = qa[i]; qB[i] = qb[i]; }
    }
    __syncthreads();

    const int baseA = ((rA >> 3) + 7) * 15 + ((rA & 7) + 7);
    const int baseB = ((rB >> 3) + 7) * 15 + ((rB & 7) + 7);
    const int idnA = ids[rA];
    const int idnB = ids[rB];
    const float* tbh = tb + h * 228;

    float sumA = 0.f, sumB = 0.f;
    ull accA[16], accB[16];
    #pragma unroll
    for (int i = 0; i < 16; i++) { accA[i] = 0ull; accB[i] = 0ull; }

    const ulonglong2* ksr = (const ulonglong2*)(ks + h * 2048);
    const ulonglong2* vsr = (const ulonglong2*)(vs + h * 2048);

    #pragma unroll 2
    for (int m = 0; m < 64; m++) {
        const ulonglong2* kk = ksr + m * 8;
        ull dA0 = 0, dA1 = 0, dB0 = 0, dB1 = 0;
        #pragma unroll
        for (int i = 0; i < 8; i++) {
            ulonglong2 kv = kk[i];
            dA0 = ffma2(qA[2 * i],     kv.x, dA0);
            dA1 = ffma2(qA[2 * i + 1], kv.y, dA1);
            dB0 = ffma2(qB[2 * i],     kv.x, dB0);
            dB1 = ffma2(qB[2 * i + 1], kv.y, dB1);
        }
        float a0, a1, a2, a3, b0, b1, b2, b3;
        upk2(dA0, a0, a1); upk2(dA1, a2, a3);
        upk2(dB0, b0, b1); upk2(dB1, b2, b3);
        int moff = (m >> 3) * 15 + (m & 7);
        int idm  = ids[m];
        float svA = (a0 + a1) + (a2 + a3) + tbh[baseA - moff]
                    - (idnA != idm ? 100.0f : 0.0f);
        float svB = (b0 + b1) + (b2 + b3) + tbh[baseB - moff]
                    - (idnB != idm ? 100.0f : 0.0f);
        float eA = __expf(svA), eB = __expf(svB);
        sumA += eA; sumB += eB;
        ull e2A = dup2(eA), e2B = dup2(eB);
        const ulonglong2* vv = vsr + m * 8;
        #pragma unroll
        for (int i = 0; i < 8; i++) {
            ulonglong2 vx = vv[i];
            accA[2 * i]     = ffma2(e2A, vx.x, accA[2 * i]);
            accA[2 * i + 1] = ffma2(e2A, vx.y, accA[2 * i + 1]);
            accB[2 * i]     = ffma2(e2B, vx.x, accB[2 * i]);
            accB[2 * i + 1] = ffma2(e2B, vx.y, accB[2 * i + 1]);
        }
    }

    const float invA = 1.0f / sumA;
    const float invB = 1.0f / sumB;
    float* oA = g_att + ((size_t)b_ * 64 + rA) * 192 + h * 32;
    float* oB = g_att + ((size_t)b_ * 64 + rB) * 192 + h * 32;
    #pragma unroll
    for (int i = 0; i < 16; i++) {
        float xx, yy;
        upk2(accA[i], xx, yy);
        *(float2*)&oA[2 * i] = make_float2(xx * invA, yy * invA);
        upk2(accB[i], xx, yy);
        *(float2*)&oB[2 * i] = make_float2(xx * invB, yy * invB);
    }
}

// =====================================================================
// Kernel 3: output projection + window-reverse + reverse roll scatter
// grid=4608, block=256, 2 CTAs/SM.
// smem: as[192][66] + wsm[192][66] = 101376 B; 3 output chunks of 64.
// =====================================================================
__global__ __launch_bounds__(256, 2)
void k_proj(const float* __restrict__ w, const float* __restrict__ bias,
            float* __restrict__ out) {
    extern __shared__ float sm[];
    float* as  = sm;               // [192][66]  (c-major, token minor)
    float* wsm = sm + 192 * 66;    // [192][66], reused per-chunk as res[64][66]
    __shared__ int soff[64];

    const int b_  = blockIdx.x;
    const int b   = b_ / 576;
    const int wh  = (b_ % 576) / 24;
    const int ww  = b_ % 24;
    const int tid = threadIdx.x;

    if (tid < 64) {
        int ph = tid >> 3, pw = tid & 7;
        int sh = wh * 8 + ph + SS_; if (sh >= H_) sh -= H_;
        int sw = ww * 8 + pw + SS_; if (sw >= W_) sw -= W_;
        soff[tid] = sh * W_ + sw;
    }

    const float* ab = g_att + (size_t)b_ * 64 * 192;
    #pragma unroll
    for (int i = 0; i < 48; i++) {
        int idx = tid + i * 256;
        int t = idx / 192, c = idx - t * 192;
        as[c * 66 + t] = ab[idx];
    }

    const int ty = tid >> 4, tx = tid & 15, t0 = ty * 4;
    float* outb = out + (size_t)b * C_ * HW_;

    for (int ch = 0; ch < 3; ch++) {
        __syncthreads();   // previous chunk scatter / as loads settled
        const float* wb = w + ch * 64 * 192;
        #pragma unroll
        for (int i = 0; i < 48; i++) {
            int idx = tid + i * 256;
            int o = idx / 192, k = idx - o * 192;
            wsm[k * 66 + o] = wb[o * 192 + k];
        }
        __syncthreads();

        ull acc[4][2];
        {
            ull b0 = *(const ull*)&bias[ch * 64 + 2 * tx];
            ull b1 = *(const ull*)&bias[ch * 64 + 2 * tx + 32];
            #pragma unroll
            for (int t = 0; t < 4; t++) { acc[t][0] = b0; acc[t][1] = b1; }
        }

        #pragma unroll 4
        for (int k = 0; k < 192; k++) {
            const ull* ar = (const ull*)&as[k * 66 + t0];
            float ax, ay, az, aw;
            upk2(ar[0], ax, ay);
            upk2(ar[1], az, aw);
            ull a0 = dup2(ax), a1 = dup2(ay), a2 = dup2(az), a3 = dup2(aw);
            const ull* wr = (const ull*)&wsm[k * 66 + 2 * tx];
            ull bv0 = wr[0], bv1 = wr[16];
            acc[0][0] = ffma2(a0, bv0, acc[0][0]);
            acc[1][0] = ffma2(a1, bv0, acc[1][0]);
            acc[2][0] = ffma2(a2, bv0, acc[2][0]);
            acc[3][0] = ffma2(a3, bv0, acc[3][0]);
            acc[0][1] = ffma2(a0, bv1, acc[0][1]);
            acc[1][1] = ffma2(a1, bv1, acc[1][1]);
            acc[2][1] = ffma2(a2, bv1, acc[2][1]);
            acc[3][1] = ffma2(a3, bv1, acc[3][1]);
        }
        __syncthreads();   // all wsm weight reads done

        float* res = wsm;  // [64][66] token-minor staging
        #pragma unroll
        for (int j = 0; j < 2; j++) {
            int ol = 2 * tx + 32 * j;
            #pragma unroll
            for (int t = 0; t < 4; t++) {
                float xx, yy;
                upk2(acc[t][j], xx, yy);
                res[ol * 66 + t0 + t]       = xx;
                res[(ol + 1) * 66 + t0 + t] = yy;
            }
        }
        __syncthreads();

        #pragma unroll
        for (int i = 0; i < 16; i++) {
            int idx = tid + i * 256;
            int o = idx >> 6, t = idx & 63;
            outb[(ch * 64 + o) * HW_ + soff[t]] = res[o * 66 + t];
        }
    }
}

// =====================================================================
extern "C" void kernel_launch(void* const* d_in, const int* in_sizes, int n_in,
                              void* d_out, int out_size) {
    const float* x      = (const float*)d_in[0];
    const float* qkv_w  = (const float*)d_in[1];
    const float* qkv_b  = (const float*)d_in[2];
    const float* proj_w = (const float*)d_in[3];
    const float* proj_b = (const float*)d_in[4];
    const float* tbl    = (const float*)d_in[5];
    float* out = (float*)d_out;

    cudaFuncSetAttribute(k_qkv,  cudaFuncAttributeMaxDynamicSharedMemorySize, 99840);
    cudaFuncSetAttribute(k_attn, cudaFuncAttributeMaxDynamicSharedMemorySize, 104032);
    cudaFuncSetAttribute(k_proj, cudaFuncAttributeMaxDynamicSharedMemorySize, 101376);

    k_qkv<<<NWIN, 256, 99840>>>(x, qkv_w, qkv_b);
    k_attn<<<NWIN, 192, 104032>>>(tbl);
    k_proj<<<NWIN, 256, 101376>>>(proj_w, proj_b, out);
}